// round 5
// baseline (speedup 1.0000x reference)
#include <cuda_runtime.h>

#define NB 8
#define NN 512
#define DD 256
#define DH 64
#define OUT_ELEMS (NB*NN*DH)            // 262144
#define E4        16777216u             // e element count / 4
#define E4_HALF   8388608u

#define QKV_BLOCKS 192                  // 3 mats * 64 row-tiles
#define COPY1 1024u
#define ATT_BLOCKS 128                  // 8 batches * 16 i-tiles of 32
#define COPY2 1024u

// dynamic smem layout for k2 (floats):
// Qs[32*64]=2048 | Ks[64*68]=4352 | Vs[64*64]=4096 | Ss[32*65]=2080
// coef[32] | l[32] | mj[64] (int)   -> total 12704 floats = 50816 B
#define K2_SMEM_BYTES 50816

__device__ float g_Q[NB*NN*DH];
__device__ float g_K[NB*NN*DH];
__device__ float g_V[NB*NN*DH];

// ---------------------------------------------------------------------------
// Kernel 1: QKV projection (tiled SGEMM) + first half of the e copy
// ---------------------------------------------------------------------------
__global__ void __launch_bounds__(256) k1_qkv_copy(
    const float* __restrict__ x, const int* __restrict__ mask,
    const float* __restrict__ Wq, const float* __restrict__ bq,
    const float* __restrict__ Wk, const float* __restrict__ bk,
    const float* __restrict__ Wv, const float* __restrict__ bv,
    const float4* __restrict__ e4, float4* __restrict__ eo4)
{
    if (blockIdx.x >= QKV_BLOCKS) {
        // streaming copy, MLP=4: first half of e. 32 f4 per thread exactly.
        unsigned cid = blockIdx.x - QKV_BLOCKS;
        unsigned i = cid * 256u + threadIdx.x;
        const unsigned S = COPY1 * 256u;          // 262144
        #pragma unroll 1
        for (int it = 0; it < 8; it++) {
            float4 a = __ldcs(e4 + i);
            float4 b = __ldcs(e4 + i + S);
            float4 c = __ldcs(e4 + i + 2u*S);
            float4 d = __ldcs(e4 + i + 3u*S);
            __stcs(eo4 + i,        a);
            __stcs(eo4 + i + S,    b);
            __stcs(eo4 + i + 2u*S, c);
            __stcs(eo4 + i + 3u*S, d);
            i += 4u*S;
        }
        return;
    }

    __shared__ float Xs[64 * 65];
    __shared__ float Ws[64 * 64];

    int which  = blockIdx.x >> 6;         // 0=Q, 1=K, 2=V
    int rowblk = blockIdx.x & 63;
    const float* W    = (which == 0) ? Wq : (which == 1) ? Wk : Wv;
    const float* bias = (which == 0) ? bq : (which == 1) ? bk : bv;
    float* outw       = (which == 0) ? g_Q : (which == 1) ? g_K : g_V;

    int t  = threadIdx.x;
    int tx = t & 15;
    int ty = t >> 4;
    int row0 = rowblk * 64;

    float acc[4][4];
    #pragma unroll
    for (int i = 0; i < 4; i++)
        #pragma unroll
        for (int j = 0; j < 4; j++) acc[i][j] = 0.f;

    for (int kt = 0; kt < 4; kt++) {
        int k0 = kt * 64;
        __syncthreads();
        #pragma unroll
        for (int idx = t; idx < 4096; idx += 256) {
            int r  = idx >> 6;
            int kk = idx & 63;
            Xs[r * 65 + kk] = x[(row0 + r) * DD + k0 + kk];
            Ws[idx]         = W[k0 * DH + idx];
        }
        __syncthreads();

        const float4* Ws4 = (const float4*)Ws;
        #pragma unroll 8
        for (int kk = 0; kk < 64; kk++) {
            float4 bv4 = Ws4[kk * 16 + tx];
            #pragma unroll
            for (int i = 0; i < 4; i++) {
                float a = Xs[(ty * 4 + i) * 65 + kk];
                acc[i][0] += a * bv4.x;
                acc[i][1] += a * bv4.y;
                acc[i][2] += a * bv4.z;
                acc[i][3] += a * bv4.w;
            }
        }
    }

    #pragma unroll
    for (int i = 0; i < 4; i++) {
        int r = row0 + ty * 4 + i;
        float m = (float)mask[r];
        float4 o;
        o.x = (acc[i][0] + bias[tx * 4 + 0]) * m;
        o.y = (acc[i][1] + bias[tx * 4 + 1]) * m;
        o.z = (acc[i][2] + bias[tx * 4 + 2]) * m;
        o.w = (acc[i][3] + bias[tx * 4 + 3]) * m;
        *(float4*)(outw + r * DH + tx * 4) = o;
    }
}

// ---------------------------------------------------------------------------
// Kernel 2: flash attention, 32 queries/block, register softmax
//           + second half of the e copy
// ---------------------------------------------------------------------------
__global__ void __launch_bounds__(256) k2_attn_copy(
    const int* __restrict__ mask, float* __restrict__ outp,
    const float4* __restrict__ e4, float4* __restrict__ eo4)
{
    if (blockIdx.x >= ATT_BLOCKS) {
        unsigned cid = blockIdx.x - ATT_BLOCKS;
        unsigned i = E4_HALF + cid * 256u + threadIdx.x;
        const unsigned S = COPY2 * 256u;
        #pragma unroll 1
        for (int it = 0; it < 8; it++) {
            float4 a = __ldcs(e4 + i);
            float4 b = __ldcs(e4 + i + S);
            float4 c = __ldcs(e4 + i + 2u*S);
            float4 d = __ldcs(e4 + i + 3u*S);
            __stcs(eo4 + i,        a);
            __stcs(eo4 + i + S,    b);
            __stcs(eo4 + i + 2u*S, c);
            __stcs(eo4 + i + 3u*S, d);
            i += 4u*S;
        }
        return;
    }

    extern __shared__ float sm[];
    float* Qs     = sm;                 // 32*64
    float* Ks     = sm + 2048;          // 64 rows * 68 (pad)
    float* Vs     = sm + 2048 + 4352;   // 64*64
    float* Ss     = sm + 2048 + 4352 + 4096;   // 32*65
    float* coef_s = sm + 12576;         // 32
    float* l_s    = sm + 12608;         // 32
    int*   mj_s   = (int*)(sm + 12640); // 64

    int blk = blockIdx.x;
    int b   = blk >> 4;
    int i0  = (blk & 15) << 5;          // 32 queries
    int t   = threadIdx.x;

    // load Q tile (512 float4)
    const float4* Qg4 = (const float4*)(g_Q + (b * NN + i0) * DH);
    ((float4*)Qs)[t]       = Qg4[t];
    ((float4*)Qs)[t + 256] = Qg4[t + 256];

    int kg   = t & 15;      // phase1: keys j = kg + 16*kk
    int qg   = t >> 4;      // phase1: queries 2*qg, 2*qg+1
    int qidx = t >> 3;      // PV: query row
    int dhg  = t & 7;       // PV: owns float4 dhg, dhg+8

    const float NEGINF = __int_as_float(0xff800000);
    float m0 = NEGINF, m1 = NEGINF, l0 = 0.f, l1 = 0.f;
    float4 o0 = make_float4(0.f,0.f,0.f,0.f);
    float4 o1 = make_float4(0.f,0.f,0.f,0.f);

    const float4* Ks4 = (const float4*)Ks;
    const float4* Qs4 = (const float4*)Qs;
    const float4* Vs4 = (const float4*)Vs;

    for (int c = 0; c < 8; c++) {
        int j0 = c * 64;
        __syncthreads();
        const float4* Kg4 = (const float4*)(g_K + (b * NN + j0) * DH);
        const float4* Vg4 = (const float4*)(g_V + (b * NN + j0) * DH);
        #pragma unroll
        for (int i = 0; i < 4; i++) {
            int idx4 = t + i * 256;
            int r  = idx4 >> 4;
            int c4 = idx4 & 15;
            ((float4*)Ks)[r * 17 + c4] = Kg4[idx4];
            ((float4*)Vs)[idx4]        = Vg4[idx4];
        }
        if (t < 64) mj_s[t] = mask[b * NN + j0 + t];
        __syncthreads();

        // ---- scores: 2 queries x 4 keys per thread ----
        float s00=0.f,s01=0.f,s02=0.f,s03=0.f;
        float s10=0.f,s11=0.f,s12=0.f,s13=0.f;
        #pragma unroll
        for (int k4 = 0; k4 < 16; k4++) {
            float4 ka = Ks4[(kg     ) * 17 + k4];
            float4 kb = Ks4[(kg + 16) * 17 + k4];
            float4 kc = Ks4[(kg + 32) * 17 + k4];
            float4 kd = Ks4[(kg + 48) * 17 + k4];
            float4 qa = Qs4[(qg * 2    ) * 16 + k4];
            float4 qb = Qs4[(qg * 2 + 1) * 16 + k4];
            s00 += qa.x*ka.x + qa.y*ka.y + qa.z*ka.z + qa.w*ka.w;
            s01 += qa.x*kb.x + qa.y*kb.y + qa.z*kb.z + qa.w*kb.w;
            s02 += qa.x*kc.x + qa.y*kc.y + qa.z*kc.z + qa.w*kc.w;
            s03 += qa.x*kd.x + qa.y*kd.y + qa.z*kd.z + qa.w*kd.w;
            s10 += qb.x*ka.x + qb.y*ka.y + qb.z*ka.z + qb.w*ka.w;
            s11 += qb.x*kb.x + qb.y*kb.y + qb.z*kb.z + qb.w*kb.w;
            s12 += qb.x*kc.x + qb.y*kc.y + qb.z*kc.z + qb.w*kc.w;
            s13 += qb.x*kd.x + qb.y*kd.y + qb.z*kd.z + qb.w*kd.w;
        }
        bool ma = mj_s[kg] != 0, mb = mj_s[kg+16] != 0,
             mc = mj_s[kg+32] != 0, md = mj_s[kg+48] != 0;
        s00 = ma ? s00*0.125f : -1.0e9f;  s01 = mb ? s01*0.125f : -1.0e9f;
        s02 = mc ? s02*0.125f : -1.0e9f;  s03 = md ? s03*0.125f : -1.0e9f;
        s10 = ma ? s10*0.125f : -1.0e9f;  s11 = mb ? s11*0.125f : -1.0e9f;
        s12 = mc ? s12*0.125f : -1.0e9f;  s13 = md ? s13*0.125f : -1.0e9f;

        // ---- online softmax in registers (16-lane row groups) ----
        float cm0 = fmaxf(fmaxf(s00, s01), fmaxf(s02, s03));
        float cm1 = fmaxf(fmaxf(s10, s11), fmaxf(s12, s13));
        #pragma unroll
        for (int off = 8; off; off >>= 1) {
            cm0 = fmaxf(cm0, __shfl_xor_sync(0xffffffffu, cm0, off));
            cm1 = fmaxf(cm1, __shfl_xor_sync(0xffffffffu, cm1, off));
        }
        float mn0 = fmaxf(m0, cm0), mn1 = fmaxf(m1, cm1);
        float c0 = __expf(m0 - mn0), c1 = __expf(m1 - mn1);
        float p00 = __expf(s00 - mn0), p01 = __expf(s01 - mn0);
        float p02 = __expf(s02 - mn0), p03 = __expf(s03 - mn0);
        float p10 = __expf(s10 - mn1), p11 = __expf(s11 - mn1);
        float p12 = __expf(s12 - mn1), p13 = __expf(s13 - mn1);
        float ps0 = p00 + p01 + p02 + p03;
        float ps1 = p10 + p11 + p12 + p13;
        #pragma unroll
        for (int off = 8; off; off >>= 1) {
            ps0 += __shfl_xor_sync(0xffffffffu, ps0, off);
            ps1 += __shfl_xor_sync(0xffffffffu, ps1, off);
        }
        l0 = l0 * c0 + ps0;  m0 = mn0;
        l1 = l1 * c1 + ps1;  m1 = mn1;

        int r0s = (qg * 2) * 65, r1s = (qg * 2 + 1) * 65;
        Ss[r0s + kg]      = p00;  Ss[r0s + kg + 16] = p01;
        Ss[r0s + kg + 32] = p02;  Ss[r0s + kg + 48] = p03;
        Ss[r1s + kg]      = p10;  Ss[r1s + kg + 16] = p11;
        Ss[r1s + kg + 32] = p12;  Ss[r1s + kg + 48] = p13;
        if (kg == 0) {
            coef_s[qg * 2]     = c0;
            coef_s[qg * 2 + 1] = c1;
        }
        __syncthreads();

        // ---- O += P @ V ----
        float cc = coef_s[qidx];
        o0.x *= cc; o0.y *= cc; o0.z *= cc; o0.w *= cc;
        o1.x *= cc; o1.y *= cc; o1.z *= cc; o1.w *= cc;
        #pragma unroll 8
        for (int j = 0; j < 64; j++) {
            float p  = Ss[qidx * 65 + j];
            float4 va = Vs4[j * 16 + dhg];
            float4 vb = Vs4[j * 16 + dhg + 8];
            o0.x += p * va.x; o0.y += p * va.y; o0.z += p * va.z; o0.w += p * va.w;
            o1.x += p * vb.x; o1.y += p * vb.y; o1.z += p * vb.z; o1.w += p * vb.w;
        }
    }

    if (kg == 0) {
        l_s[qg * 2]     = l0;
        l_s[qg * 2 + 1] = l1;
    }
    __syncthreads();

    float l  = l_s[qidx];
    int   mi = mask[b * NN + i0 + qidx];
    float inv = mi ? (1.f / l) : 0.f;
    float4 w0 = make_float4(o0.x*inv, o0.y*inv, o0.z*inv, o0.w*inv);
    float4 w1 = make_float4(o1.x*inv, o1.y*inv, o1.z*inv, o1.w*inv);
    float4* out4 = (float4*)outp;
    out4[(b * NN + i0 + qidx) * 16 + dhg]     = w0;
    out4[(b * NN + i0 + qidx) * 16 + dhg + 8] = w1;
}

// ---------------------------------------------------------------------------
extern "C" void kernel_launch(void* const* d_in, const int* in_sizes, int n_in,
                              void* d_out, int out_size)
{
    const float* x    = (const float*)d_in[0];
    const float* e    = (const float*)d_in[1];
    const int*   mask = (const int*)  d_in[2];
    const float* Wq   = (const float*)d_in[3];
    const float* bq   = (const float*)d_in[4];
    const float* Wk   = (const float*)d_in[5];
    const float* bk   = (const float*)d_in[6];
    const float* Wv   = (const float*)d_in[7];
    const float* bv   = (const float*)d_in[8];

    float* outp = (float*)d_out;
    const float4* e4 = (const float4*)e;
    float4* eo4 = (float4*)(outp + OUT_ELEMS);

    cudaFuncSetAttribute(k2_attn_copy,
                         cudaFuncAttributeMaxDynamicSharedMemorySize,
                         K2_SMEM_BYTES);

    k1_qkv_copy<<<QKV_BLOCKS + COPY1, 256>>>(x, mask, Wq, bq, Wk, bk, Wv, bv, e4, eo4);
    k2_attn_copy<<<ATT_BLOCKS + COPY2, 256, K2_SMEM_BYTES>>>(mask, outp, e4, eo4);
}